// round 5
// baseline (speedup 1.0000x reference)
#include <cuda_runtime.h>
#include <cuda_bf16.h>
#include <cuda_fp8.h>

#define NN 8192
#define TEMPER 0.2f

// Scratch (static __device__ arrays per harness rules)
static __device__ unsigned char g_Q8[(size_t)NN * NN];  // 64 MB fp8 e4m3 Q
static __device__ float g_part[512][NN];                // 16 MB per-block col partials
static __device__ float g_colAccS[4][NN];               // sliced accumulators
static __device__ float g_V[NN];
static __device__ float g_U[NN];
static __device__ unsigned int g_minBits;
static __device__ double g_sum;
static __device__ double g_sumsq;
static __device__ float g_minv;
static __device__ float g_kscale;

// ---------------------------------------------------------------- helpers
__device__ __forceinline__ float2 f8x2_to_f2(unsigned int s) {
    __half2_raw hr = __nv_cvt_fp8x2_to_halfraw2((__nv_fp8x2_storage_t)s, __NV_E4M3);
    return __half22float2(*reinterpret_cast<__half2*>(&hr));
}

// ---------------------------------------------------------------- init
__global__ void k_init() {
    int i = blockIdx.x * blockDim.x + threadIdx.x;
    if (i < NN) {
        g_colAccS[0][i] = 0.0f;
        g_colAccS[1][i] = 0.0f;
        g_colAccS[2][i] = 0.0f;
        g_colAccS[3][i] = 0.0f;
    }
    if (i == 0) {
        g_minBits = 0x7f800000u;
        g_sum = 0.0;
        g_sumsq = 0.0;
    }
}

// ---------------------------------------------------------------- reduce: min / sum / sumsq
__global__ void __launch_bounds__(256) k_reduce(const float* __restrict__ c) {
    const size_t total4 = (size_t)NN * NN / 4;
    const size_t stride = (size_t)gridDim.x * blockDim.x;
    double s = 0.0, ss = 0.0;
    float mn = 3.402823466e38f;
    for (size_t i = (size_t)blockIdx.x * blockDim.x + threadIdx.x; i < total4; i += stride) {
        float4 v = reinterpret_cast<const float4*>(c)[i];
        float cs  = (v.x + v.y) + (v.z + v.w);
        float css = fmaf(v.x, v.x, fmaf(v.y, v.y, fmaf(v.z, v.z, v.w * v.w)));
        s  += (double)cs;
        ss += (double)css;
        mn = fminf(mn, fminf(fminf(v.x, v.y), fminf(v.z, v.w)));
    }
    for (int o = 16; o > 0; o >>= 1) {
        s  += __shfl_down_sync(0xffffffffu, s, o);
        ss += __shfl_down_sync(0xffffffffu, ss, o);
        mn = fminf(mn, __shfl_down_sync(0xffffffffu, mn, o));
    }
    __shared__ double sh_s[8], sh_ss[8];
    __shared__ float sh_m[8];
    int warp = threadIdx.x >> 5, lane = threadIdx.x & 31;
    if (lane == 0) { sh_s[warp] = s; sh_ss[warp] = ss; sh_m[warp] = mn; }
    __syncthreads();
    if (threadIdx.x < 8) {
        s = sh_s[threadIdx.x]; ss = sh_ss[threadIdx.x]; mn = sh_m[threadIdx.x];
        for (int o = 4; o > 0; o >>= 1) {
            s  += __shfl_down_sync(0xffu, s, o);
            ss += __shfl_down_sync(0xffu, ss, o);
            mn = fminf(mn, __shfl_down_sync(0xffu, mn, o));
        }
        if (threadIdx.x == 0) {
            atomicAdd(&g_sum, s);
            atomicAdd(&g_sumsq, ss);
            atomicMin(&g_minBits, __float_as_uint(mn));
        }
    }
}

// ---------------------------------------------------------------- scalar finalize
__global__ void k_scalars() {
    double n = (double)NN * (double)NN;
    double var = (g_sumsq - g_sum * g_sum / n) / (n - 1.0);
    float stdv = (float)sqrt(var);
    g_minv = __uint_as_float(g_minBits);
    g_kscale = 1.0f / (stdv * TEMPER);
}

// ---------------------------------------------------------------- build Q8 (fp8) + exact colsum
__global__ void __launch_bounds__(256) k_build8(const float* __restrict__ c) {
    const float minv = g_minv, kk = g_kscale;
    int col0 = (blockIdx.x * 256 + threadIdx.x) * 4;
    int row0 = blockIdx.y * 64;
    float a0 = 0.f, a1 = 0.f, a2 = 0.f, a3 = 0.f;
    for (int r = 0; r < 64; ++r) {
        size_t base = (size_t)(row0 + r) * NN + col0;
        float4 v = *reinterpret_cast<const float4*>(c + base);
        float q0 = __expf((minv - v.x) * kk);
        float q1 = __expf((minv - v.y) * kk);
        float q2 = __expf((minv - v.z) * kk);
        float q3 = __expf((minv - v.w) * kk);
        a0 += q0; a1 += q1; a2 += q2; a3 += q3;
        float2 p0; p0.x = q0; p0.y = q1;
        float2 p1; p1.x = q2; p1.y = q3;
        unsigned int lo = __nv_cvt_float2_to_fp8x2(p0, __NV_SATFINITE, __NV_E4M3);
        unsigned int hi = __nv_cvt_float2_to_fp8x2(p1, __NV_SATFINITE, __NV_E4M3);
        *reinterpret_cast<unsigned int*>(g_Q8 + base) = (hi << 16) | (lo & 0xffffu);
    }
    float* ca = g_colAccS[blockIdx.y & 3];
    atomicAdd(&ca[col0 + 0], a0);
    atomicAdd(&ca[col0 + 1], a1);
    atomicAdd(&ca[col0 + 2], a2);
    atomicAdd(&ca[col0 + 3], a3);
}

// ---------------------------------------------------------------- V = B / sum(slices) ; slices = 0
__global__ void k_vfin(const float* __restrict__ B) {
    int j = blockIdx.x * blockDim.x + threadIdx.x;
    if (j < NN) {
        float s = (g_colAccS[0][j] + g_colAccS[1][j]) + (g_colAccS[2][j] + g_colAccS[3][j]);
        g_V[j] = B[j] / s;
        g_colAccS[0][j] = 0.0f;
        g_colAccS[1][j] = 0.0f;
        g_colAccS[2][j] = 0.0f;
        g_colAccS[3][j] = 0.0f;
    }
}

// ---------------------------------------------------------------- FUSED pass:
// phase 1: U for the block's 16 rows (warp = 2 rows, conflict-free V in SMEM)
// phase 2: re-scan same 16-row slab (L2-hot), per-block col partials -> g_part
__global__ void __launch_bounds__(256) k_fused8(const float* __restrict__ A) {
    __shared__ float sV[NN];
    __shared__ float sUs[16];
    int tid = threadIdx.x;
#pragma unroll
    for (int i = 0; i < 8; ++i)
        reinterpret_cast<float4*>(sV)[tid + i * 256] =
            reinterpret_cast<const float4*>(g_V)[tid + i * 256];
    __syncthreads();
    int warp = tid >> 5, lane = tid & 31;
    int rowBase = blockIdx.x * 16;
    int row0 = rowBase + warp * 2;

    // ---- phase 1: dots
    {
        const unsigned int* q0 = reinterpret_cast<const unsigned int*>(g_Q8 + (size_t)row0 * NN);
        const unsigned int* q1 = reinterpret_cast<const unsigned int*>(g_Q8 + (size_t)(row0 + 1) * NN);
        const float4* v4 = reinterpret_cast<const float4*>(sV);
        float acc0 = 0.f, acc1 = 0.f;
#pragma unroll
        for (int s = 0; s < 64; s += 4) {
            unsigned int a[4], b[4];
#pragma unroll
            for (int u = 0; u < 4; ++u) {
                a[u] = q0[lane + (s + u) * 32];
                b[u] = q1[lane + (s + u) * 32];
            }
#pragma unroll
            for (int u = 0; u < 4; ++u) {
                float4 v = v4[lane + (s + u) * 32];
                float2 lo = f8x2_to_f2(a[u] & 0xffffu);
                float2 hi = f8x2_to_f2(a[u] >> 16);
                acc0 = fmaf(lo.x, v.x, acc0);
                acc0 = fmaf(lo.y, v.y, acc0);
                acc0 = fmaf(hi.x, v.z, acc0);
                acc0 = fmaf(hi.y, v.w, acc0);
                float2 lo1 = f8x2_to_f2(b[u] & 0xffffu);
                float2 hi1 = f8x2_to_f2(b[u] >> 16);
                acc1 = fmaf(lo1.x, v.x, acc1);
                acc1 = fmaf(lo1.y, v.y, acc1);
                acc1 = fmaf(hi1.x, v.z, acc1);
                acc1 = fmaf(hi1.y, v.w, acc1);
            }
        }
        for (int o = 16; o > 0; o >>= 1) {
            acc0 += __shfl_down_sync(0xffffffffu, acc0, o);
            acc1 += __shfl_down_sync(0xffffffffu, acc1, o);
        }
        if (lane == 0) {
            sUs[warp * 2]     = __ldg(A + row0) / acc0;
            sUs[warp * 2 + 1] = __ldg(A + row0 + 1) / acc1;
            if (blockIdx.x == 0 && warp == 0) { /* keep U path for U9 consistency */ }
            g_U[row0]     = sUs[warp * 2];
            g_U[row0 + 1] = sUs[warp * 2 + 1];
        }
    }
    __syncthreads();

    // ---- phase 2: col partials. warp w owns cols [w*1024, w*1024+1024);
    // lane l: group A = w*1024 + l*16, group B = A + 512. Coalesced LDG.128.
    {
        int colA = warp * 1024 + lane * 16;
        int colB = colA + 512;
        float a[16], b[16];
#pragma unroll
        for (int i = 0; i < 16; ++i) { a[i] = 0.f; b[i] = 0.f; }
        const unsigned char* slab = g_Q8 + (size_t)rowBase * NN;
#pragma unroll 4
        for (int r = 0; r < 16; ++r) {
            float ur = sUs[r];
            uint4 wA = *reinterpret_cast<const uint4*>(slab + (size_t)r * NN + colA);
            uint4 wB = *reinterpret_cast<const uint4*>(slab + (size_t)r * NN + colB);
            const unsigned int* pa = reinterpret_cast<const unsigned int*>(&wA);
            const unsigned int* pb = reinterpret_cast<const unsigned int*>(&wB);
#pragma unroll
            for (int k = 0; k < 4; ++k) {
                float2 lo = f8x2_to_f2(pa[k] & 0xffffu);
                float2 hi = f8x2_to_f2(pa[k] >> 16);
                a[k * 4 + 0] = fmaf(lo.x, ur, a[k * 4 + 0]);
                a[k * 4 + 1] = fmaf(lo.y, ur, a[k * 4 + 1]);
                a[k * 4 + 2] = fmaf(hi.x, ur, a[k * 4 + 2]);
                a[k * 4 + 3] = fmaf(hi.y, ur, a[k * 4 + 3]);
                float2 lo1 = f8x2_to_f2(pb[k] & 0xffffu);
                float2 hi1 = f8x2_to_f2(pb[k] >> 16);
                b[k * 4 + 0] = fmaf(lo1.x, ur, b[k * 4 + 0]);
                b[k * 4 + 1] = fmaf(lo1.y, ur, b[k * 4 + 1]);
                b[k * 4 + 2] = fmaf(hi1.x, ur, b[k * 4 + 2]);
                b[k * 4 + 3] = fmaf(hi1.y, ur, b[k * 4 + 3]);
            }
        }
        float* pr = g_part[blockIdx.x];
#pragma unroll
        for (int k = 0; k < 4; ++k)
            *reinterpret_cast<float4*>(pr + colA + k * 4) =
                make_float4(a[k * 4 + 0], a[k * 4 + 1], a[k * 4 + 2], a[k * 4 + 3]);
#pragma unroll
        for (int k = 0; k < 4; ++k)
            *reinterpret_cast<float4*>(pr + colB + k * 4) =
                make_float4(b[k * 4 + 0], b[k * 4 + 1], b[k * 4 + 2], b[k * 4 + 3]);
    }
}

// ---------------------------------------------------------------- psum: slices += sum of 512 partials
// grid (32 colchunks, 16 bchunks) x 256 threads; coalesced reads, atomic finish
__global__ void __launch_bounds__(256) k_psum() {
    int tid = threadIdx.x;
    int col = blockIdx.x * 256 + tid;
    int b0 = blockIdx.y * 32;
    float s = 0.f;
#pragma unroll 8
    for (int r = 0; r < 32; ++r)
        s += g_part[b0 + r][col];
    atomicAdd(&g_colAccS[blockIdx.y & 3][col], s);
}

// ---------------------------------------------------------------- U = A / (Q8 V)  (standalone, for U9)
__global__ void __launch_bounds__(256) k_rowmv8(const float* __restrict__ A) {
    __shared__ float sV[NN];
    int tid = threadIdx.x;
#pragma unroll
    for (int i = 0; i < 8; ++i)
        reinterpret_cast<float4*>(sV)[tid + i * 256] =
            reinterpret_cast<const float4*>(g_V)[tid + i * 256];
    __syncthreads();
    int warp = tid >> 5, lane = tid & 31;
    int row0 = blockIdx.x * 16 + warp * 2;
    const unsigned int* q0 = reinterpret_cast<const unsigned int*>(g_Q8 + (size_t)row0 * NN);
    const unsigned int* q1 = reinterpret_cast<const unsigned int*>(g_Q8 + (size_t)(row0 + 1) * NN);
    const float4* v4 = reinterpret_cast<const float4*>(sV);
    float acc0 = 0.f, acc1 = 0.f;
#pragma unroll
    for (int s = 0; s < 64; s += 4) {
        unsigned int a[4], b[4];
#pragma unroll
        for (int u = 0; u < 4; ++u) {
            a[u] = q0[lane + (s + u) * 32];
            b[u] = q1[lane + (s + u) * 32];
        }
#pragma unroll
        for (int u = 0; u < 4; ++u) {
            float4 v = v4[lane + (s + u) * 32];
            float2 lo = f8x2_to_f2(a[u] & 0xffffu);
            float2 hi = f8x2_to_f2(a[u] >> 16);
            acc0 = fmaf(lo.x, v.x, acc0);
            acc0 = fmaf(lo.y, v.y, acc0);
            acc0 = fmaf(hi.x, v.z, acc0);
            acc0 = fmaf(hi.y, v.w, acc0);
            float2 lo1 = f8x2_to_f2(b[u] & 0xffffu);
            float2 hi1 = f8x2_to_f2(b[u] >> 16);
            acc1 = fmaf(lo1.x, v.x, acc1);
            acc1 = fmaf(lo1.y, v.y, acc1);
            acc1 = fmaf(hi1.x, v.z, acc1);
            acc1 = fmaf(hi1.y, v.w, acc1);
        }
    }
    for (int o = 16; o > 0; o >>= 1) {
        acc0 += __shfl_down_sync(0xffffffffu, acc0, o);
        acc1 += __shfl_down_sync(0xffffffffu, acc1, o);
    }
    if (lane == 0) {
        g_U[row0]     = __ldg(A + row0) / acc0;
        g_U[row0 + 1] = __ldg(A + row0 + 1) / acc1;
    }
}

// ---------------------------------------------------------------- exact colmv (for V10): slices += Q^T U, Q from cdist
__global__ void __launch_bounds__(256) k_colmv_exact(const float* __restrict__ c) {
    __shared__ float sU[64];
    int tid = threadIdx.x;
    int rb = blockIdx.x >> 3;
    int col0 = (blockIdx.x & 7) * 1024 + tid * 4;
    int row0 = rb * 64;
    if (tid < 64) sU[tid] = g_U[row0 + tid];
    __syncthreads();
    const float minv = g_minv, kk = g_kscale;
    const float* cp = c + (size_t)row0 * NN + col0;
    float a0 = 0.f, a1 = 0.f, a2 = 0.f, a3 = 0.f;
#pragma unroll 4
    for (int r = 0; r < 64; ++r) {
        float4 v = *reinterpret_cast<const float4*>(cp + (size_t)r * NN);
        float u = sU[r];
        a0 = fmaf(__expf((minv - v.x) * kk), u, a0);
        a1 = fmaf(__expf((minv - v.y) * kk), u, a1);
        a2 = fmaf(__expf((minv - v.z) * kk), u, a2);
        a3 = fmaf(__expf((minv - v.w) * kk), u, a3);
    }
    float* ca = g_colAccS[rb & 3];
    atomicAdd(&ca[col0 + 0], a0);
    atomicAdd(&ca[col0 + 1], a1);
    atomicAdd(&ca[col0 + 2], a2);
    atomicAdd(&ca[col0 + 3], a3);
}

// ---------------------------------------------------------------- final: exact Q, fused U10, write T
__global__ void __launch_bounds__(256) k_final(const float* __restrict__ c,
                                               const float* __restrict__ A,
                                               float* __restrict__ out) {
    __shared__ float sV[NN];
    __shared__ float sred[8];
    __shared__ float sbc;
    int tid = threadIdx.x;
#pragma unroll
    for (int i = 0; i < 8; ++i)
        reinterpret_cast<float4*>(sV)[tid + i * 256] =
            reinterpret_cast<const float4*>(g_V)[tid + i * 256];
    __syncthreads();
    const float minv = g_minv, kk = g_kscale;
    for (int row = blockIdx.x; row < NN; row += gridDim.x) {
        const float4* crow = reinterpret_cast<const float4*>(c + (size_t)row * NN);
        float4 qv[8];
        float s = 0.f;
#pragma unroll
        for (int k = 0; k < 8; ++k) {
            int j = tid * 4 + k * 1024;
            float4 v  = crow[tid + k * 256];
            float4 vv = *reinterpret_cast<const float4*>(sV + j);
            float q0 = __expf((minv - v.x) * kk) * vv.x;
            float q1 = __expf((minv - v.y) * kk) * vv.y;
            float q2 = __expf((minv - v.z) * kk) * vv.z;
            float q3 = __expf((minv - v.w) * kk) * vv.w;
            qv[k].x = q0; qv[k].y = q1; qv[k].z = q2; qv[k].w = q3;
            s += (q0 + q1) + (q2 + q3);
        }
        for (int o = 16; o > 0; o >>= 1)
            s += __shfl_down_sync(0xffffffffu, s, o);
        if ((tid & 31) == 0) sred[tid >> 5] = s;
        __syncthreads();
        if (tid < 32) {
            float t = (tid < 8) ? sred[tid] : 0.f;
            for (int o = 4; o > 0; o >>= 1)
                t += __shfl_down_sync(0xffffffffu, t, o);
            if (tid == 0) sbc = __ldg(A + row) / t;
        }
        __syncthreads();
        float scale = sbc;
        float4* orow = reinterpret_cast<float4*>(out + (size_t)row * NN);
#pragma unroll
        for (int k = 0; k < 8; ++k) {
            float4 w = qv[k];
            w.x *= scale; w.y *= scale; w.z *= scale; w.w *= scale;
            orow[tid + k * 256] = w;
        }
        __syncthreads();
    }
}

// ---------------------------------------------------------------- launch
extern "C" void kernel_launch(void* const* d_in, const int* in_sizes, int n_in,
                              void* d_out, int out_size) {
    const float* cdist = (const float*)d_in[0];
    const float* A     = (const float*)d_in[1];
    const float* B     = (const float*)d_in[2];
    float* out = (float*)d_out;

    k_init<<<32, 256>>>();
    k_reduce<<<1184, 256>>>(cdist);
    k_scalars<<<1, 1>>>();
    k_build8<<<dim3(8, 128), 256>>>(cdist);   // Q8 (fp8), exact colsum -> slices
    k_vfin<<<32, 256>>>(B);                   // V1
    for (int it = 1; it <= 8; ++it) {
        k_fused8<<<512, 256>>>(A);            // U_it + col partials in ONE Q8 pass
        k_psum<<<dim3(32, 16), 256>>>();      // slices = sum(partials)
        k_vfin<<<32, 256>>>(B);               // V_{it+1}
    }
    k_rowmv8<<<512, 256>>>(A);                // U9
    k_colmv_exact<<<1024, 256>>>(cdist);      // slices = Q^T U9 (exact)
    k_vfin<<<32, 256>>>(B);                   // V10 (accurate)
    // U10 fused into output: exact fp32 Q, T = (A_i/(Q V10)_i) * Q_ij * V10_j
    k_final<<<444, 256>>>(cdist, A, out);
}